// round 1
// baseline (speedup 1.0000x reference)
#include <cuda_runtime.h>
#include <cuda_bf16.h>
#include <cstdint>
#include <cstdio>

// Problem constants
#define T_SEQ 512
#define B_SZ  64
#define E_SZ  512
#define L_NUM 2
#define G3E   1536          // 3*E

// ---------------- device scratch (no allocations allowed) ----------------
__device__ float g_x[T_SEQ * B_SZ * E_SZ];        // embeddings, then layer-1 outputs (reused)
__device__ float g_xproj[T_SEQ * B_SZ * G3E];     // per-layer input projections
__device__ float g_h[B_SZ * E_SZ];                // hidden state
__device__ unsigned g_bar_count;
__device__ unsigned g_bar_gen;

// ---------------- grid barrier (monotonic generation, wrap-safe) ----------------
__device__ __forceinline__ void grid_barrier(unsigned nctas, unsigned* sphase) {
    __syncthreads();
    if (threadIdx.x == 0) {
        unsigned ph = *sphase + 1u;
        __threadfence();
        if (atomicAdd(&g_bar_count, 1u) == nctas - 1u) {
            g_bar_count = 0u;
            asm volatile("st.release.gpu.u32 [%0], %1;" :: "l"(&g_bar_gen), "r"(ph) : "memory");
        } else {
            unsigned cur;
            do {
                asm volatile("ld.acquire.gpu.u32 %0, [%1];" : "=r"(cur) : "l"(&g_bar_gen) : "memory");
            } while ((int)(cur - ph) < 0);
        }
        *sphase = ph;
    }
    __syncthreads();
}

// ---------------- embedding gather ----------------
__global__ void embed_kernel(const int* __restrict__ idx,
                             const float* __restrict__ emb,
                             float* __restrict__ out) {
    int i = blockIdx.x * blockDim.x + threadIdx.x;     // float4 index
    const int total = T_SEQ * B_SZ * (E_SZ / 4);
    if (i >= total) return;
    int row = i >> 7;          // / (E/4=128)
    int col = i & 127;
    int tok = idx[row];
    reinterpret_cast<float4*>(out)[i] =
        reinterpret_cast<const float4*>(emb)[(size_t)tok * 128 + col];
}

// ---------------- fp32 GEMM: C[M,N] = A[M,K] * B[N,K]^T + bias[N] ----------------
// M=32768, N=1536, K=512. 128x128 tile, BK=16, 256 threads, 8x8 microtile.
#define BM 128
#define BN 128
#define BK 16

__global__ __launch_bounds__(256) void gemm_nt_bias(
    const float* __restrict__ A, const float* __restrict__ Bm,
    const float* __restrict__ bias, float* __restrict__ C,
    int M, int N, int K) {
    __shared__ float As[BK][BM];
    __shared__ float Bs[BK][BN];

    const int tid = threadIdx.x;
    const int bm = blockIdx.y * BM;
    const int bn = blockIdx.x * BN;
    const int tx = tid & 15;        // 0..15
    const int ty = tid >> 4;        // 0..15

    float acc[8][8];
#pragma unroll
    for (int i = 0; i < 8; i++)
#pragma unroll
        for (int j = 0; j < 8; j++) acc[i][j] = 0.f;

    for (int k0 = 0; k0 < K; k0 += BK) {
#pragma unroll
        for (int it = 0; it < 2; it++) {
            int f = tid + it * 256;            // 0..511
            int row = f >> 2;                  // 0..127
            int kq = (f & 3) << 2;             // 0,4,8,12
            float4 va = *reinterpret_cast<const float4*>(&A[(size_t)(bm + row) * K + k0 + kq]);
            As[kq + 0][row] = va.x; As[kq + 1][row] = va.y;
            As[kq + 2][row] = va.z; As[kq + 3][row] = va.w;
            float4 vb = *reinterpret_cast<const float4*>(&Bm[(size_t)(bn + row) * K + k0 + kq]);
            Bs[kq + 0][row] = vb.x; Bs[kq + 1][row] = vb.y;
            Bs[kq + 2][row] = vb.z; Bs[kq + 3][row] = vb.w;
        }
        __syncthreads();

#pragma unroll
        for (int k = 0; k < BK; k++) {
            float4 a0 = *reinterpret_cast<const float4*>(&As[k][ty * 8]);
            float4 a1 = *reinterpret_cast<const float4*>(&As[k][ty * 8 + 4]);
            float4 b0 = *reinterpret_cast<const float4*>(&Bs[k][tx * 8]);
            float4 b1 = *reinterpret_cast<const float4*>(&Bs[k][tx * 8 + 4]);
            float av[8] = {a0.x, a0.y, a0.z, a0.w, a1.x, a1.y, a1.z, a1.w};
            float bv[8] = {b0.x, b0.y, b0.z, b0.w, b1.x, b1.y, b1.z, b1.w};
#pragma unroll
            for (int i = 0; i < 8; i++)
#pragma unroll
                for (int j = 0; j < 8; j++) acc[i][j] += av[i] * bv[j];
        }
        __syncthreads();
    }

    float4 bias0 = *reinterpret_cast<const float4*>(&bias[bn + tx * 8]);
    float4 bias1 = *reinterpret_cast<const float4*>(&bias[bn + tx * 8 + 4]);
#pragma unroll
    for (int i = 0; i < 8; i++) {
        int row = bm + ty * 8 + i;
        float* cp = &C[(size_t)row * N + bn + tx * 8];
        float4 v0, v1;
        v0.x = acc[i][0] + bias0.x; v0.y = acc[i][1] + bias0.y;
        v0.z = acc[i][2] + bias0.z; v0.w = acc[i][3] + bias0.w;
        v1.x = acc[i][4] + bias1.x; v1.y = acc[i][5] + bias1.y;
        v1.z = acc[i][6] + bias1.z; v1.w = acc[i][7] + bias1.w;
        *reinterpret_cast<float4*>(cp) = v0;
        *reinterpret_cast<float4*>(cp + 4) = v1;
    }
}

// ---------------- persistent GRU recurrence ----------------
// Grid = 128 CTAs = 8 batch-groups x 16 e-groups, 256 threads.
// CTA (bg, eg): batch rows bg*8..bg*8+7, e columns eg*32..eg*32+31.
// Thread (warp b = tid/32, lane jg = tid%32) owns (b, e=ebase+jg) and all 3 gates.
// Smem: 96 W_hh rows (interleaved [e][gate], row stride 517 -> conflict-free)
//       + 8x512 h tile.
#define RGRID 128
#define EGROUPS 16
#define BTILE 8
#define ESLICE 32
#define WROWS 96
#define WSTR 517
#define RSMEM_FLOATS (WROWS * WSTR + BTILE * E_SZ)
#define RSMEM_BYTES (RSMEM_FLOATS * 4)

__global__ __launch_bounds__(256, 1) void gru_recur_kernel(
    const float* __restrict__ xproj,   // [T,64,1536]
    const float* __restrict__ Whh,     // [1536,512] (this layer)
    const float* __restrict__ bhh,     // [1536]
    const int* __restrict__ lens,      // [64]
    float* __restrict__ hbuf,          // [64,512]
    float* __restrict__ ybuf,          // [T,64,512]
    float* __restrict__ finals)        // [64,512]
{
    extern __shared__ float smem[];
    float* sh_w = smem;                       // WROWS * WSTR
    float* sh_h = smem + WROWS * WSTR;        // BTILE * 512
    __shared__ unsigned s_phase;

    const int tid = threadIdx.x;
    const int cta = blockIdx.x;
    const int bg = cta / EGROUPS;
    const int eg = cta % EGROUPS;
    const int ebase = eg * ESLICE;
    const int b = tid >> 5;            // local batch row 0..7
    const int jg = tid & 31;           // local e 0..31
    const int bglob = bg * BTILE + b;
    const int e = ebase + jg;

    if (tid == 0) {
        unsigned cur;
        asm volatile("ld.acquire.gpu.u32 %0, [%1];" : "=r"(cur) : "l"(&g_bar_gen) : "memory");
        s_phase = cur;
    }

    // Load this CTA's 96 weight rows, interleaved: local row j = elocal*3 + gate
    for (int idx = tid; idx < WROWS * E_SZ; idx += 256) {
        int j = idx >> 9;          // / 512
        int k = idx & 511;
        int el = j / 3, gate = j - el * 3;
        sh_w[j * WSTR + k] = Whh[(size_t)(gate * E_SZ + ebase + el) * E_SZ + k];
    }

    const float bh0 = bhh[0 * E_SZ + e];
    const float bh1 = bhh[1 * E_SZ + e];
    const float bh2 = bhh[2 * E_SZ + e];
    const int mylen = lens[bglob];

    // zero our slice of h, then sync whole grid (also covers weight smem via barrier's syncthreads)
    hbuf[bglob * E_SZ + e] = 0.f;
    grid_barrier(RGRID, &s_phase);

    const float* wp0 = sh_w + (jg * 3 + 0) * WSTR;
    const float* wp1 = wp0 + WSTR;
    const float* wp2 = wp1 + WSTR;
    const float* hp = sh_h + b * E_SZ;

    float hnew = 0.f;

    for (int t = 0; t < T_SEQ; t++) {
        // Stage h tile (8 rows x 512) into smem, coalesced float4
        {
            const float4* hsrc = reinterpret_cast<const float4*>(hbuf + bg * BTILE * E_SZ);
            float4* hdst = reinterpret_cast<float4*>(sh_h);
#pragma unroll
            for (int i = 0; i < 4; i++) hdst[tid + i * 256] = hsrc[tid + i * 256];
        }
        __syncthreads();

        // prefetch x-projection (independent of the dot loop)
        const float* xp = xproj + ((size_t)t * B_SZ + bglob) * G3E;
        float xr = xp[e];
        float xz = xp[E_SZ + e];
        float xn = xp[2 * E_SZ + e];

        // 3 dot products of length 512 from smem
        float a0 = 0.f, a1 = 0.f, a2 = 0.f;
#pragma unroll 16
        for (int k = 0; k < E_SZ; k++) {
            float hv = hp[k];
            a0 += hv * wp0[k];
            a1 += hv * wp1[k];
            a2 += hv * wp2[k];
        }

        float hr = a0 + bh0, hz = a1 + bh1, hn = a2 + bh2;
        float r = 1.f / (1.f + expf(-(xr + hr)));
        float z = 1.f / (1.f + expf(-(xz + hz)));
        float n = tanhf(xn + r * hn);
        float hprev = hp[e];
        bool m = (t < mylen);
        hnew = m ? ((1.f - z) * n + z * hprev) : hprev;

        hbuf[bglob * E_SZ + e] = hnew;
        ybuf[((size_t)t * B_SZ + bglob) * E_SZ + e] = m ? hnew : 0.f;

        grid_barrier(RGRID, &s_phase);
    }

    finals[bglob * E_SZ + e] = hnew;
}

// ---------------- launch ----------------
extern "C" void kernel_launch(void* const* d_in, const int* in_sizes, int n_in,
                              void* d_out, int out_size) {
    const int*   input_batch = (const int*)d_in[0];
    const int*   lens        = (const int*)d_in[1];
    const float* emb         = (const float*)d_in[2];
    const float* W_ih        = (const float*)d_in[3];
    const float* W_hh        = (const float*)d_in[4];
    const float* b_ih        = (const float*)d_in[5];
    const float* b_hh        = (const float*)d_in[6];
    float* out = (float*)d_out;

    void* p;
    cudaGetSymbolAddress(&p, g_x);     float* gx  = (float*)p;
    cudaGetSymbolAddress(&p, g_xproj); float* gxp = (float*)p;
    cudaGetSymbolAddress(&p, g_h);     float* gh  = (float*)p;

    cudaFuncSetAttribute(gru_recur_kernel,
                         cudaFuncAttributeMaxDynamicSharedMemorySize, RSMEM_BYTES);

    const int M = T_SEQ * B_SZ;        // 32768
    const size_t out_x_elems = (size_t)T_SEQ * B_SZ * E_SZ;   // 16777216
    float* finals0 = out + out_x_elems;
    float* finals1 = out + out_x_elems + B_SZ * E_SZ;

    // 1. embeddings
    {
        int total = T_SEQ * B_SZ * (E_SZ / 4);
        embed_kernel<<<(total + 255) / 256, 256>>>(input_batch, emb, gx);
    }
    // 2. layer 0 input projection
    gemm_nt_bias<<<dim3(G3E / BN, M / BM), 256>>>(gx, W_ih, b_ih, gxp, M, G3E, E_SZ);
    // 3. layer 0 recurrence: y -> gx (reuse), finals -> d_out hidden[0]
    gru_recur_kernel<<<RGRID, 256, RSMEM_BYTES>>>(gxp, W_hh, b_hh, lens, gh, gx, finals0);
    // 4. layer 1 input projection
    gemm_nt_bias<<<dim3(G3E / BN, M / BM), 256>>>(gx, W_ih + (size_t)G3E * E_SZ,
                                                  b_ih + G3E, gxp, M, G3E, E_SZ);
    // 5. layer 1 recurrence: y -> d_out[0:T*B*E], finals -> d_out hidden[1]
    gru_recur_kernel<<<RGRID, 256, RSMEM_BYTES>>>(gxp, W_hh + (size_t)G3E * E_SZ,
                                                  b_hh + G3E, lens, gh, out, finals1);
}

// round 2
// speedup vs baseline: 1.5661x; 1.5661x over previous
#include <cuda_runtime.h>
#include <cuda_bf16.h>
#include <cstdint>
#include <cstdio>

// Problem constants
#define T_SEQ 512
#define B_SZ  64
#define E_SZ  512
#define L_NUM 2
#define G3E   1536          // 3*E

// ---------------- device scratch (no allocations allowed) ----------------
__device__ float g_x[T_SEQ * B_SZ * E_SZ];        // embeddings, then layer-1 outputs (reused)
__device__ float g_xproj[T_SEQ * B_SZ * G3E];     // per-layer input projections
__device__ float g_h[B_SZ * E_SZ];                // hidden state
__device__ unsigned g_bar_count;
__device__ unsigned g_bar_gen;

// ---------------- f32x2 helpers (sm_103a packed fp32 math) ----------------
__device__ __forceinline__ void fma2(unsigned long long& d, unsigned long long a,
                                     unsigned long long b) {
    asm("fma.rn.f32x2 %0, %1, %2, %3;" : "=l"(d) : "l"(a), "l"(b), "l"(d));
}
__device__ __forceinline__ float f32x2_sum(unsigned long long v) {
    return __uint_as_float((unsigned)v) + __uint_as_float((unsigned)(v >> 32));
}
__device__ __forceinline__ unsigned long long dup2(float x) {
    unsigned long long r; unsigned u = __float_as_uint(x);
    asm("mov.b64 %0, {%1, %1};" : "=l"(r) : "r"(u));
    return r;
}

// ---------------- grid barrier (monotonic generation, wrap-safe) ----------------
__device__ __forceinline__ void grid_barrier(unsigned nctas, unsigned* sphase) {
    __syncthreads();
    if (threadIdx.x == 0) {
        unsigned ph = *sphase + 1u;
        __threadfence();
        if (atomicAdd(&g_bar_count, 1u) == nctas - 1u) {
            g_bar_count = 0u;
            asm volatile("st.release.gpu.u32 [%0], %1;" :: "l"(&g_bar_gen), "r"(ph) : "memory");
        } else {
            unsigned cur;
            do {
                asm volatile("ld.acquire.gpu.u32 %0, [%1];" : "=r"(cur) : "l"(&g_bar_gen) : "memory");
            } while ((int)(cur - ph) < 0);
        }
        *sphase = ph;
    }
    __syncthreads();
}

// ---------------- embedding gather ----------------
__global__ void embed_kernel(const int* __restrict__ idx,
                             const float* __restrict__ emb,
                             float* __restrict__ out) {
    int i = blockIdx.x * blockDim.x + threadIdx.x;     // float4 index
    const int total = T_SEQ * B_SZ * (E_SZ / 4);
    if (i >= total) return;
    int row = i >> 7;          // / (E/4=128)
    int col = i & 127;
    int tok = idx[row];
    reinterpret_cast<float4*>(out)[i] =
        reinterpret_cast<const float4*>(emb)[(size_t)tok * 128 + col];
}

// ---------------- fp32 GEMM: C[M,N] = A[M,K] * B[N,K]^T + bias[N] ----------------
// M=32768, N=1536, K=512. 128x128 tile, BK=16, 256 threads, 8x8 microtile.
// Math done with packed f32x2: A row-pairs come straight from the As float4,
// B columns are duplicated into both lanes.
#define BM 128
#define BN 128
#define BK 16

__global__ __launch_bounds__(256) void gemm_nt_bias(
    const float* __restrict__ A, const float* __restrict__ Bm,
    const float* __restrict__ bias, float* __restrict__ C,
    int M, int N, int K) {
    __shared__ float As[BK][BM];
    __shared__ float Bs[BK][BN];

    const int tid = threadIdx.x;
    const int bm = blockIdx.y * BM;
    const int bn = blockIdx.x * BN;
    const int tx = tid & 15;        // 0..15
    const int ty = tid >> 4;        // 0..15

    unsigned long long acc2[4][8];   // [row-pair ip][col j]: rows (ty*8+2ip, +1)
#pragma unroll
    for (int i = 0; i < 4; i++)
#pragma unroll
        for (int j = 0; j < 8; j++) acc2[i][j] = 0ULL;

    for (int k0 = 0; k0 < K; k0 += BK) {
#pragma unroll
        for (int it = 0; it < 2; it++) {
            int f = tid + it * 256;            // 0..511
            int row = f >> 2;                  // 0..127
            int kq = (f & 3) << 2;             // 0,4,8,12
            float4 va = *reinterpret_cast<const float4*>(&A[(size_t)(bm + row) * K + k0 + kq]);
            As[kq + 0][row] = va.x; As[kq + 1][row] = va.y;
            As[kq + 2][row] = va.z; As[kq + 3][row] = va.w;
            float4 vb = *reinterpret_cast<const float4*>(&Bm[(size_t)(bn + row) * K + k0 + kq]);
            Bs[kq + 0][row] = vb.x; Bs[kq + 1][row] = vb.y;
            Bs[kq + 2][row] = vb.z; Bs[kq + 3][row] = vb.w;
        }
        __syncthreads();

#pragma unroll
        for (int k = 0; k < BK; k++) {
            ulonglong2 aq0 = *reinterpret_cast<const ulonglong2*>(&As[k][ty * 8]);
            ulonglong2 aq1 = *reinterpret_cast<const ulonglong2*>(&As[k][ty * 8 + 4]);
            float4 b0 = *reinterpret_cast<const float4*>(&Bs[k][tx * 8]);
            float4 b1 = *reinterpret_cast<const float4*>(&Bs[k][tx * 8 + 4]);
            unsigned long long ap[4] = {aq0.x, aq0.y, aq1.x, aq1.y};
            unsigned long long bd[8] = {dup2(b0.x), dup2(b0.y), dup2(b0.z), dup2(b0.w),
                                        dup2(b1.x), dup2(b1.y), dup2(b1.z), dup2(b1.w)};
#pragma unroll
            for (int ip = 0; ip < 4; ip++)
#pragma unroll
                for (int j = 0; j < 8; j++) fma2(acc2[ip][j], ap[ip], bd[j]);
        }
        __syncthreads();
    }

    float bv[8];
    {
        float4 bias0 = *reinterpret_cast<const float4*>(&bias[bn + tx * 8]);
        float4 bias1 = *reinterpret_cast<const float4*>(&bias[bn + tx * 8 + 4]);
        bv[0] = bias0.x; bv[1] = bias0.y; bv[2] = bias0.z; bv[3] = bias0.w;
        bv[4] = bias1.x; bv[5] = bias1.y; bv[6] = bias1.z; bv[7] = bias1.w;
    }
#pragma unroll
    for (int ip = 0; ip < 4; ip++) {
        float lo[8], hi[8];
#pragma unroll
        for (int j = 0; j < 8; j++) {
            lo[j] = __uint_as_float((unsigned)acc2[ip][j]) + bv[j];
            hi[j] = __uint_as_float((unsigned)(acc2[ip][j] >> 32)) + bv[j];
        }
        int row0 = bm + ty * 8 + 2 * ip;
        float* cp0 = &C[(size_t)row0 * N + bn + tx * 8];
        float* cp1 = cp0 + N;
        *reinterpret_cast<float4*>(cp0)     = make_float4(lo[0], lo[1], lo[2], lo[3]);
        *reinterpret_cast<float4*>(cp0 + 4) = make_float4(lo[4], lo[5], lo[6], lo[7]);
        *reinterpret_cast<float4*>(cp1)     = make_float4(hi[0], hi[1], hi[2], hi[3]);
        *reinterpret_cast<float4*>(cp1 + 4) = make_float4(hi[4], hi[5], hi[6], hi[7]);
    }
}

// ---------------- persistent GRU recurrence ----------------
// Grid = 128 CTAs = 8 batch-groups x 16 e-groups, 256 threads = 8 warps.
// CTA (bg, eg): batch rows bg*8..bg*8+7, e columns eg*32..eg*32+31.
// Dot phase: warp w handles k-slice [w*64, w*64+64) for ALL 8 batch rows;
//            lane jg owns column e = ebase + jg (3 gates x 8 b f32x2 accumulators).
//            Weights are read once per warp and reused across the 8 batch rows;
//            h values are warp-broadcast.
// Reduce phase: thread (b = tid>>5, jg = tid&31) sums the 8 warp-partials per gate.
// Smem: 96 W_hh rows interleaved [e][gate], row stride 516 floats
//       (3*516 = 1548 == 12 mod 32 -> 8-lane LDS.128 phases cover all 32 banks);
//       h tile (8x512) overlapped with the partial-sum buffer (8x768).
#define RGRID 128
#define EGROUPS 16
#define BTILE 8
#define ESLICE 32
#define WROWS 96
#define WSTR 516
#define PART_FLOATS (8 * 3 * BTILE * ESLICE)         // 6144
#define RSMEM_FLOATS (WROWS * WSTR + PART_FLOATS)    // 49536 + 6144
#define RSMEM_BYTES (RSMEM_FLOATS * 4)

__global__ __launch_bounds__(256, 1) void gru_recur_kernel(
    const float* __restrict__ xproj,   // [T,64,1536]
    const float* __restrict__ Whh,     // [1536,512] (this layer)
    const float* __restrict__ bhh,     // [1536]
    const int* __restrict__ lens,      // [64]
    float* __restrict__ hbuf,          // [64,512]
    float* __restrict__ ybuf,          // [T,64,512]
    float* __restrict__ finals)        // [64,512]
{
    extern __shared__ float smem[];
    float* sh_w = smem;                       // WROWS * WSTR
    float* sh_h = smem + WROWS * WSTR;        // 8*512 floats (dot phase)
    float* sh_part = sh_h;                    // 8*768 floats (reduce phase, overlapped)
    __shared__ unsigned s_phase;

    const int tid = threadIdx.x;
    const int cta = blockIdx.x;
    const int bg = cta / EGROUPS;
    const int eg = cta % EGROUPS;
    const int ebase = eg * ESLICE;
    const int w = tid >> 5;            // dot phase: k-slice warp 0..7
    const int jg = tid & 31;           // lane = local e 0..31
    const int bR = w;                  // reduce phase: local batch row 0..7
    const int bglob = bg * BTILE + bR;
    const int e = ebase + jg;
    const int kbase = w * 64;

    if (tid == 0) {
        unsigned cur;
        asm volatile("ld.acquire.gpu.u32 %0, [%1];" : "=r"(cur) : "l"(&g_bar_gen) : "memory");
        s_phase = cur;
    }

    // Load this CTA's 96 weight rows (float4), interleaved: row j = elocal*3 + gate
    for (int idx = tid; idx < WROWS * (E_SZ / 4); idx += 256) {
        int j = idx >> 7;                 // / 128
        int kq = (idx & 127) << 2;
        int el = j / 3, gate = j - el * 3;
        *reinterpret_cast<float4*>(&sh_w[j * WSTR + kq]) =
            *reinterpret_cast<const float4*>(&Whh[(size_t)(gate * E_SZ + ebase + el) * E_SZ + kq]);
    }

    const float bh0 = bhh[0 * E_SZ + e];
    const float bh1 = bhh[1 * E_SZ + e];
    const float bh2 = bhh[2 * E_SZ + e];
    const int mylen = lens[bglob];

    // zero our slice of h, then sync whole grid
    hbuf[bglob * E_SZ + e] = 0.f;
    grid_barrier(RGRID, &s_phase);

    const float* wp0 = sh_w + (jg * 3 + 0) * WSTR;
    const float* wp1 = wp0 + WSTR;
    const float* wp2 = wp1 + WSTR;

    float hnew = 0.f;

    for (int t = 0; t < T_SEQ; t++) {
        // Stage h tile (8 rows x 512) into smem, coalesced float4
        {
            const float4* hsrc = reinterpret_cast<const float4*>(hbuf + bg * BTILE * E_SZ);
            float4* hdst = reinterpret_cast<float4*>(sh_h);
#pragma unroll
            for (int i = 0; i < 4; i++) hdst[tid + i * 256] = hsrc[tid + i * 256];
        }

        // prefetch x-projection for the reduce phase (independent LDGs)
        const float* xp = xproj + ((size_t)t * B_SZ + bglob) * G3E;
        float xr = xp[e];
        float xz = xp[E_SZ + e];
        float xn = xp[2 * E_SZ + e];

        __syncthreads();

        float hprev = sh_h[bR * E_SZ + e];   // read before partials overwrite the region

        // ---- dot phase: 64 k x 3 gates x 8 batch, f32x2 packed ----
        unsigned long long a0[8], a1[8], a2[8];
#pragma unroll
        for (int b = 0; b < 8; b++) { a0[b] = 0ULL; a1[b] = 0ULL; a2[b] = 0ULL; }

#pragma unroll 4
        for (int kk = 0; kk < 16; kk++) {
            int k4 = kbase + kk * 4;
            ulonglong2 w0 = *reinterpret_cast<const ulonglong2*>(wp0 + k4);
            ulonglong2 w1 = *reinterpret_cast<const ulonglong2*>(wp1 + k4);
            ulonglong2 w2 = *reinterpret_cast<const ulonglong2*>(wp2 + k4);
#pragma unroll
            for (int b = 0; b < 8; b++) {
                ulonglong2 h2 = *reinterpret_cast<const ulonglong2*>(sh_h + b * E_SZ + k4);
                fma2(a0[b], h2.x, w0.x); fma2(a0[b], h2.y, w0.y);
                fma2(a1[b], h2.x, w1.x); fma2(a1[b], h2.y, w1.y);
                fma2(a2[b], h2.x, w2.x); fma2(a2[b], h2.y, w2.y);
            }
        }

        __syncthreads();   // all warps done reading sh_h

        // ---- store partials: part[w][gate][b][lane] ----
        {
            float* pw = sh_part + w * (3 * BTILE * ESLICE);
#pragma unroll
            for (int b = 0; b < 8; b++) {
                pw[(0 * BTILE + b) * ESLICE + jg] = f32x2_sum(a0[b]);
                pw[(1 * BTILE + b) * ESLICE + jg] = f32x2_sum(a1[b]);
                pw[(2 * BTILE + b) * ESLICE + jg] = f32x2_sum(a2[b]);
            }
        }
        __syncthreads();

        // ---- reduce phase: thread (bR, jg) sums 8 warp partials per gate ----
        float s0 = 0.f, s1 = 0.f, s2 = 0.f;
#pragma unroll
        for (int ww = 0; ww < 8; ww++) {
            const float* pw = sh_part + ww * (3 * BTILE * ESLICE);
            s0 += pw[(0 * BTILE + bR) * ESLICE + jg];
            s1 += pw[(1 * BTILE + bR) * ESLICE + jg];
            s2 += pw[(2 * BTILE + bR) * ESLICE + jg];
        }

        float hr = s0 + bh0, hz = s1 + bh1, hn = s2 + bh2;
        float r = 1.f / (1.f + expf(-(xr + hr)));
        float z = 1.f / (1.f + expf(-(xz + hz)));
        float n = tanhf(xn + r * hn);
        bool m = (t < mylen);
        hnew = m ? ((1.f - z) * n + z * hprev) : hprev;

        hbuf[bglob * E_SZ + e] = hnew;
        ybuf[((size_t)t * B_SZ + bglob) * E_SZ + e] = m ? hnew : 0.f;

        grid_barrier(RGRID, &s_phase);
    }

    finals[bglob * E_SZ + e] = hnew;
}

// ---------------- launch ----------------
extern "C" void kernel_launch(void* const* d_in, const int* in_sizes, int n_in,
                              void* d_out, int out_size) {
    const int*   input_batch = (const int*)d_in[0];
    const int*   lens        = (const int*)d_in[1];
    const float* emb         = (const float*)d_in[2];
    const float* W_ih        = (const float*)d_in[3];
    const float* W_hh        = (const float*)d_in[4];
    const float* b_ih        = (const float*)d_in[5];
    const float* b_hh        = (const float*)d_in[6];
    float* out = (float*)d_out;

    void* p;
    cudaGetSymbolAddress(&p, g_x);     float* gx  = (float*)p;
    cudaGetSymbolAddress(&p, g_xproj); float* gxp = (float*)p;
    cudaGetSymbolAddress(&p, g_h);     float* gh  = (float*)p;

    cudaFuncSetAttribute(gru_recur_kernel,
                         cudaFuncAttributeMaxDynamicSharedMemorySize, RSMEM_BYTES);

    const int M = T_SEQ * B_SZ;        // 32768
    const size_t out_x_elems = (size_t)T_SEQ * B_SZ * E_SZ;   // 16777216
    float* finals0 = out + out_x_elems;
    float* finals1 = out + out_x_elems + B_SZ * E_SZ;

    // 1. embeddings
    {
        int total = T_SEQ * B_SZ * (E_SZ / 4);
        embed_kernel<<<(total + 255) / 256, 256>>>(input_batch, emb, gx);
    }
    // 2. layer 0 input projection
    gemm_nt_bias<<<dim3(G3E / BN, M / BM), 256>>>(gx, W_ih, b_ih, gxp, M, G3E, E_SZ);
    // 3. layer 0 recurrence: y -> gx (reuse), finals -> d_out hidden[0]
    gru_recur_kernel<<<RGRID, 256, RSMEM_BYTES>>>(gxp, W_hh, b_hh, lens, gh, gx, finals0);
    // 4. layer 1 input projection
    gemm_nt_bias<<<dim3(G3E / BN, M / BM), 256>>>(gx, W_ih + (size_t)G3E * E_SZ,
                                                  b_ih + G3E, gxp, M, G3E, E_SZ);
    // 5. layer 1 recurrence: y -> d_out[0:T*B*E], finals -> d_out hidden[1]
    gru_recur_kernel<<<RGRID, 256, RSMEM_BYTES>>>(gxp, W_hh + (size_t)G3E * E_SZ,
                                                  b_hh + G3E, lens, gh, out, finals1);
}

// round 3
// speedup vs baseline: 1.7279x; 1.1034x over previous
#include <cuda_runtime.h>
#include <cuda_bf16.h>
#include <cstdint>
#include <cstdio>

// Problem constants
#define T_SEQ 512
#define B_SZ  64
#define E_SZ  512
#define L_NUM 2
#define G3E   1536          // 3*E

// ---------------- device scratch (no allocations allowed) ----------------
__device__ float g_x[T_SEQ * B_SZ * E_SZ];        // embeddings, then layer-1 outputs (reused)
__device__ float g_xproj[T_SEQ * B_SZ * G3E];     // per-layer input projections
__device__ float g_h[B_SZ * E_SZ];                // hidden state
__device__ unsigned g_bar[8];                     // per-batch-group monotonic barrier counters

// ---------------- f32x2 helpers (sm_103a packed fp32 math) ----------------
__device__ __forceinline__ void fma2(unsigned long long& d, unsigned long long a,
                                     unsigned long long b) {
    asm("fma.rn.f32x2 %0, %1, %2, %3;" : "=l"(d) : "l"(a), "l"(b), "l"(d));
}
__device__ __forceinline__ float f32x2_sum(unsigned long long v) {
    return __uint_as_float((unsigned)v) + __uint_as_float((unsigned)(v >> 32));
}
__device__ __forceinline__ unsigned long long dup2(float x) {
    unsigned long long r; unsigned u = __float_as_uint(x);
    asm("mov.b64 %0, {%1, %1};" : "=l"(r) : "r"(u));
    return r;
}

// ---------------- embedding gather (+ barrier counter reset) ----------------
__global__ void embed_kernel(const int* __restrict__ idx,
                             const float* __restrict__ emb,
                             float* __restrict__ out) {
    if (blockIdx.x == 0 && threadIdx.x < 8) g_bar[threadIdx.x] = 0u;   // reset per launch/replay
    int i = blockIdx.x * blockDim.x + threadIdx.x;     // float4 index
    const int total = T_SEQ * B_SZ * (E_SZ / 4);
    if (i >= total) return;
    int row = i >> 7;          // / (E/4=128)
    int col = i & 127;
    int tok = idx[row];
    reinterpret_cast<float4*>(out)[i] =
        reinterpret_cast<const float4*>(emb)[(size_t)tok * 128 + col];
}

// ---------------- fp32 GEMM: C[M,N] = A[M,K] * B[N,K]^T + bias[N] ----------------
// M=32768, N=1536, K=512. 128x128 tile, BK=16, 256 threads, 8x8 microtile.
// f32x2 math (A row-pairs native, B dup'd). Register double-buffered global loads.
#define BM 128
#define BN 128
#define BK 16

__global__ __launch_bounds__(256) void gemm_nt_bias(
    const float* __restrict__ A, const float* __restrict__ Bm,
    const float* __restrict__ bias, float* __restrict__ C,
    int M, int N, int K) {
    __shared__ float As[BK][BM];
    __shared__ float Bs[BK][BN];

    const int tid = threadIdx.x;
    const int bm = blockIdx.y * BM;
    const int bn = blockIdx.x * BN;
    const int tx = tid & 15;        // 0..15
    const int ty = tid >> 4;        // 0..15

    // staging indices for the two load slots
    const int f0 = tid;             // 0..255
    const int f1 = tid + 256;       // 256..511
    const int r0 = f0 >> 2, kq0 = (f0 & 3) << 2;
    const int r1 = f1 >> 2, kq1 = (f1 & 3) << 2;

    unsigned long long acc2[4][8];   // [row-pair ip][col j]: rows (ty*8+2ip, +1)
#pragma unroll
    for (int i = 0; i < 4; i++)
#pragma unroll
        for (int j = 0; j < 8; j++) acc2[i][j] = 0ULL;

    // prefetch first tile into registers
    float4 pa0 = *reinterpret_cast<const float4*>(&A[(size_t)(bm + r0) * K + kq0]);
    float4 pa1 = *reinterpret_cast<const float4*>(&A[(size_t)(bm + r1) * K + kq1]);
    float4 pb0 = *reinterpret_cast<const float4*>(&Bm[(size_t)(bn + r0) * K + kq0]);
    float4 pb1 = *reinterpret_cast<const float4*>(&Bm[(size_t)(bn + r1) * K + kq1]);

    for (int k0 = 0; k0 < K; k0 += BK) {
        // store staged tile
        As[kq0 + 0][r0] = pa0.x; As[kq0 + 1][r0] = pa0.y;
        As[kq0 + 2][r0] = pa0.z; As[kq0 + 3][r0] = pa0.w;
        As[kq1 + 0][r1] = pa1.x; As[kq1 + 1][r1] = pa1.y;
        As[kq1 + 2][r1] = pa1.z; As[kq1 + 3][r1] = pa1.w;
        Bs[kq0 + 0][r0] = pb0.x; Bs[kq0 + 1][r0] = pb0.y;
        Bs[kq0 + 2][r0] = pb0.z; Bs[kq0 + 3][r0] = pb0.w;
        Bs[kq1 + 0][r1] = pb1.x; Bs[kq1 + 1][r1] = pb1.y;
        Bs[kq1 + 2][r1] = pb1.z; Bs[kq1 + 3][r1] = pb1.w;
        __syncthreads();

        // prefetch next tile (overlaps with FMA loop below)
        if (k0 + BK < K) {
            int kn = k0 + BK;
            pa0 = *reinterpret_cast<const float4*>(&A[(size_t)(bm + r0) * K + kn + kq0]);
            pa1 = *reinterpret_cast<const float4*>(&A[(size_t)(bm + r1) * K + kn + kq1]);
            pb0 = *reinterpret_cast<const float4*>(&Bm[(size_t)(bn + r0) * K + kn + kq0]);
            pb1 = *reinterpret_cast<const float4*>(&Bm[(size_t)(bn + r1) * K + kn + kq1]);
        }

#pragma unroll
        for (int k = 0; k < BK; k++) {
            ulonglong2 aq0 = *reinterpret_cast<const ulonglong2*>(&As[k][ty * 8]);
            ulonglong2 aq1 = *reinterpret_cast<const ulonglong2*>(&As[k][ty * 8 + 4]);
            float4 b0 = *reinterpret_cast<const float4*>(&Bs[k][tx * 8]);
            float4 b1 = *reinterpret_cast<const float4*>(&Bs[k][tx * 8 + 4]);
            unsigned long long ap[4] = {aq0.x, aq0.y, aq1.x, aq1.y};
            unsigned long long bd[8] = {dup2(b0.x), dup2(b0.y), dup2(b0.z), dup2(b0.w),
                                        dup2(b1.x), dup2(b1.y), dup2(b1.z), dup2(b1.w)};
#pragma unroll
            for (int ip = 0; ip < 4; ip++)
#pragma unroll
                for (int j = 0; j < 8; j++) fma2(acc2[ip][j], ap[ip], bd[j]);
        }
        __syncthreads();
    }

    float bv[8];
    {
        float4 bias0 = *reinterpret_cast<const float4*>(&bias[bn + tx * 8]);
        float4 bias1 = *reinterpret_cast<const float4*>(&bias[bn + tx * 8 + 4]);
        bv[0] = bias0.x; bv[1] = bias0.y; bv[2] = bias0.z; bv[3] = bias0.w;
        bv[4] = bias1.x; bv[5] = bias1.y; bv[6] = bias1.z; bv[7] = bias1.w;
    }
#pragma unroll
    for (int ip = 0; ip < 4; ip++) {
        float lo[8], hi[8];
#pragma unroll
        for (int j = 0; j < 8; j++) {
            lo[j] = __uint_as_float((unsigned)acc2[ip][j]) + bv[j];
            hi[j] = __uint_as_float((unsigned)(acc2[ip][j] >> 32)) + bv[j];
        }
        int row0 = bm + ty * 8 + 2 * ip;
        float* cp0 = &C[(size_t)row0 * N + bn + tx * 8];
        float* cp1 = cp0 + N;
        *reinterpret_cast<float4*>(cp0)     = make_float4(lo[0], lo[1], lo[2], lo[3]);
        *reinterpret_cast<float4*>(cp0 + 4) = make_float4(lo[4], lo[5], lo[6], lo[7]);
        *reinterpret_cast<float4*>(cp1)     = make_float4(hi[0], hi[1], hi[2], hi[3]);
        *reinterpret_cast<float4*>(cp1 + 4) = make_float4(hi[4], hi[5], hi[6], hi[7]);
    }
}

// ---------------- persistent GRU recurrence ----------------
// Grid = 128 CTAs = 8 batch-groups x 16 e-groups, 256 threads = 8 warps.
// Batch groups are fully independent -> each bg has its own monotonic barrier
// counter; only the 16 eg-CTAs of a bg synchronize with each other.
// Dot phase: warp w handles k-slice [w*64, w*64+64) for ALL 8 batch rows.
// Reduce phase: thread (b = tid>>5, jg = tid&31) sums the 8 warp-partials/gate.
#define RGRID 128
#define EGROUPS 16
#define BTILE 8
#define ESLICE 32
#define WROWS 96
#define WSTR 516
#define PART_FLOATS (8 * 3 * BTILE * ESLICE)         // 6144
#define RSMEM_FLOATS (WROWS * WSTR + PART_FLOATS)
#define RSMEM_BYTES (RSMEM_FLOATS * 4)

__device__ __forceinline__ void bg_arrive(unsigned* ctr) {
    asm volatile("red.release.gpu.global.add.u32 [%0], %1;" :: "l"(ctr), "r"(1u) : "memory");
}
__device__ __forceinline__ void bg_wait(unsigned* ctr, unsigned target) {
    unsigned cur;
    do {
        asm volatile("ld.acquire.gpu.u32 %0, [%1];" : "=r"(cur) : "l"(ctr) : "memory");
    } while ((int)(cur - target) < 0);
}

__global__ __launch_bounds__(256, 1) void gru_recur_kernel(
    const float* __restrict__ xproj,   // [T,64,1536]
    const float* __restrict__ Whh,     // [1536,512] (this layer)
    const float* __restrict__ bhh,     // [1536]
    const int* __restrict__ lens,      // [64]
    float* __restrict__ hbuf,          // [64,512]
    float* __restrict__ ybuf,          // [T,64,512]
    float* __restrict__ finals,        // [64,512]
    int epoch)                         // layer index (barrier target base)
{
    extern __shared__ float smem[];
    float* sh_w = smem;                       // WROWS * WSTR
    float* sh_h = smem + WROWS * WSTR;        // 8*512 floats (dot phase)
    float* sh_part = sh_h;                    // 8*768 floats (reduce phase, overlapped)

    const int tid = threadIdx.x;
    const int cta = blockIdx.x;
    const int bg = cta / EGROUPS;
    const int eg = cta % EGROUPS;
    const int ebase = eg * ESLICE;
    const int w = tid >> 5;            // dot phase: k-slice warp 0..7
    const int jg = tid & 31;           // lane = local e 0..31
    const int bR = w;                  // reduce phase: local batch row 0..7
    const int bglob = bg * BTILE + bR;
    const int e = ebase + jg;
    const int kbase = w * 64;
    unsigned* ctr = &g_bar[bg];
    const unsigned tbase = (unsigned)epoch * (16u * (T_SEQ + 1)) + 16u;

    // Load this CTA's 96 weight rows (float4), interleaved: row j = elocal*3 + gate
    for (int idx = tid; idx < WROWS * (E_SZ / 4); idx += 256) {
        int j = idx >> 7;                 // / 128
        int kq = (idx & 127) << 2;
        int el = j / 3, gate = j - el * 3;
        *reinterpret_cast<float4*>(&sh_w[j * WSTR + kq]) =
            *reinterpret_cast<const float4*>(&Whh[(size_t)(gate * E_SZ + ebase + el) * E_SZ + kq]);
    }

    const float bh0 = bhh[0 * E_SZ + e];
    const float bh1 = bhh[1 * E_SZ + e];
    const float bh2 = bhh[2 * E_SZ + e];
    const int mylen = lens[bglob];

    // zero our slice of h, arrive, prefetch xp(t=0), wait for the 16 eg-CTAs
    hbuf[bglob * E_SZ + e] = 0.f;
    __syncthreads();                 // everyone's store issued before tid0 signals
    if (tid == 0) bg_arrive(ctr);

    float xr, xz, xn;
    {
        const float* xp = xproj + ((size_t)0 * B_SZ + bglob) * G3E;
        xr = xp[e]; xz = xp[E_SZ + e]; xn = xp[2 * E_SZ + e];
    }
    if (tid == 0) bg_wait(ctr, tbase);
    __syncthreads();

    const float* wp0 = sh_w + (jg * 3 + 0) * WSTR;
    const float* wp1 = wp0 + WSTR;
    const float* wp2 = wp1 + WSTR;

    float hnew = 0.f;

    for (int t = 0; t < T_SEQ; t++) {
        // Stage h tile (8 rows x 512) into smem, coalesced float4
        {
            const float4* hsrc = reinterpret_cast<const float4*>(hbuf + bg * BTILE * E_SZ);
            float4* hdst = reinterpret_cast<float4*>(sh_h);
#pragma unroll
            for (int i = 0; i < 4; i++) hdst[tid + i * 256] = hsrc[tid + i * 256];
        }
        __syncthreads();

        float hprev = sh_h[bR * E_SZ + e];   // read before partials overwrite region

        // ---- dot phase: 64 k x 3 gates x 8 batch, f32x2 packed ----
        unsigned long long a0[8], a1[8], a2[8];
#pragma unroll
        for (int b = 0; b < 8; b++) { a0[b] = 0ULL; a1[b] = 0ULL; a2[b] = 0ULL; }

#pragma unroll 4
        for (int kk = 0; kk < 16; kk++) {
            int k4 = kbase + kk * 4;
            ulonglong2 w0 = *reinterpret_cast<const ulonglong2*>(wp0 + k4);
            ulonglong2 w1 = *reinterpret_cast<const ulonglong2*>(wp1 + k4);
            ulonglong2 w2 = *reinterpret_cast<const ulonglong2*>(wp2 + k4);
#pragma unroll
            for (int b = 0; b < 8; b++) {
                ulonglong2 h2 = *reinterpret_cast<const ulonglong2*>(sh_h + b * E_SZ + k4);
                fma2(a0[b], h2.x, w0.x); fma2(a0[b], h2.y, w0.y);
                fma2(a1[b], h2.x, w1.x); fma2(a1[b], h2.y, w1.y);
                fma2(a2[b], h2.x, w2.x); fma2(a2[b], h2.y, w2.y);
            }
        }

        __syncthreads();   // all warps done reading sh_h

        // ---- store partials: part[w][gate][b][lane] ----
        {
            float* pw = sh_part + w * (3 * BTILE * ESLICE);
#pragma unroll
            for (int b = 0; b < 8; b++) {
                pw[(0 * BTILE + b) * ESLICE + jg] = f32x2_sum(a0[b]);
                pw[(1 * BTILE + b) * ESLICE + jg] = f32x2_sum(a1[b]);
                pw[(2 * BTILE + b) * ESLICE + jg] = f32x2_sum(a2[b]);
            }
        }
        __syncthreads();

        // ---- reduce phase: thread (bR, jg) sums 8 warp partials per gate ----
        float s0 = 0.f, s1 = 0.f, s2 = 0.f;
#pragma unroll
        for (int ww = 0; ww < 8; ww++) {
            const float* pw = sh_part + ww * (3 * BTILE * ESLICE);
            s0 += pw[(0 * BTILE + bR) * ESLICE + jg];
            s1 += pw[(1 * BTILE + bR) * ESLICE + jg];
            s2 += pw[(2 * BTILE + bR) * ESLICE + jg];
        }

        float hr = s0 + bh0, hz = s1 + bh1, hn = s2 + bh2;
        float r = 1.f / (1.f + expf(-(xr + hr)));
        float z = 1.f / (1.f + expf(-(xz + hz)));
        float n = tanhf(xn + r * hn);
        bool m = (t < mylen);
        hnew = m ? ((1.f - z) * n + z * hprev) : hprev;

        hbuf[bglob * E_SZ + e] = hnew;

        __syncthreads();                // all h stores issued before the signal
        if (tid == 0) bg_arrive(ctr);

        // overlap with barrier wait: y store + next xp prefetch
        ybuf[((size_t)t * B_SZ + bglob) * E_SZ + e] = m ? hnew : 0.f;
        if (t + 1 < T_SEQ) {
            const float* xp = xproj + ((size_t)(t + 1) * B_SZ + bglob) * G3E;
            xr = xp[e]; xz = xp[E_SZ + e]; xn = xp[2 * E_SZ + e];
        }

        if (tid == 0) bg_wait(ctr, tbase + 16u * (t + 1));
        __syncthreads();
    }

    finals[bglob * E_SZ + e] = hnew;
}

// ---------------- launch ----------------
extern "C" void kernel_launch(void* const* d_in, const int* in_sizes, int n_in,
                              void* d_out, int out_size) {
    const int*   input_batch = (const int*)d_in[0];
    const int*   lens        = (const int*)d_in[1];
    const float* emb         = (const float*)d_in[2];
    const float* W_ih        = (const float*)d_in[3];
    const float* W_hh        = (const float*)d_in[4];
    const float* b_ih        = (const float*)d_in[5];
    const float* b_hh        = (const float*)d_in[6];
    float* out = (float*)d_out;

    void* p;
    cudaGetSymbolAddress(&p, g_x);     float* gx  = (float*)p;
    cudaGetSymbolAddress(&p, g_xproj); float* gxp = (float*)p;
    cudaGetSymbolAddress(&p, g_h);     float* gh  = (float*)p;

    cudaFuncSetAttribute(gru_recur_kernel,
                         cudaFuncAttributeMaxDynamicSharedMemorySize, RSMEM_BYTES);

    const int M = T_SEQ * B_SZ;        // 32768
    const size_t out_x_elems = (size_t)T_SEQ * B_SZ * E_SZ;   // 16777216
    float* finals0 = out + out_x_elems;
    float* finals1 = out + out_x_elems + B_SZ * E_SZ;

    // 1. embeddings (+ barrier reset)
    {
        int total = T_SEQ * B_SZ * (E_SZ / 4);
        embed_kernel<<<(total + 255) / 256, 256>>>(input_batch, emb, gx);
    }
    // 2. layer 0 input projection
    gemm_nt_bias<<<dim3(G3E / BN, M / BM), 256>>>(gx, W_ih, b_ih, gxp, M, G3E, E_SZ);
    // 3. layer 0 recurrence: y -> gx (reuse), finals -> d_out hidden[0]
    gru_recur_kernel<<<RGRID, 256, RSMEM_BYTES>>>(gxp, W_hh, b_hh, lens, gh, gx, finals0, 0);
    // 4. layer 1 input projection
    gemm_nt_bias<<<dim3(G3E / BN, M / BM), 256>>>(gx, W_ih + (size_t)G3E * E_SZ,
                                                  b_ih + G3E, gxp, M, G3E, E_SZ);
    // 5. layer 1 recurrence: y -> d_out[0:T*B*E], finals -> d_out hidden[1]
    gru_recur_kernel<<<RGRID, 256, RSMEM_BYTES>>>(gxp, W_hh + (size_t)G3E * E_SZ,
                                                  b_hh + G3E, lens, gh, out, finals1, 1);
}

// round 4
// speedup vs baseline: 1.7313x; 1.0019x over previous
#include <cuda_runtime.h>
#include <cuda_bf16.h>
#include <cstdint>
#include <cstdio>

// Problem constants
#define T_SEQ 512
#define B_SZ  64
#define E_SZ  512
#define L_NUM 2
#define G3E   1536          // 3*E

// ---------------- device scratch (no allocations allowed) ----------------
__device__ float g_x[T_SEQ * B_SZ * E_SZ];        // embeddings, then layer-1 outputs (reused)
__device__ float g_xproj[T_SEQ * B_SZ * G3E];     // per-layer input projections
__device__ float g_h[B_SZ * E_SZ];                // hidden state
__device__ unsigned g_bar[8];                     // per-batch-group monotonic barrier counters

// ---------------- f32x2 helpers (sm_103a packed fp32 math) ----------------
__device__ __forceinline__ void fma2(unsigned long long& d, unsigned long long a,
                                     unsigned long long b) {
    asm("fma.rn.f32x2 %0, %1, %2, %3;" : "=l"(d) : "l"(a), "l"(b), "l"(d));
}
__device__ __forceinline__ float f32x2_sum(unsigned long long v) {
    return __uint_as_float((unsigned)v) + __uint_as_float((unsigned)(v >> 32));
}
__device__ __forceinline__ unsigned long long dup2(float x) {
    unsigned long long r; unsigned u = __float_as_uint(x);
    asm("mov.b64 %0, {%1, %1};" : "=l"(r) : "r"(u));
    return r;
}

// ---------------- embedding gather (+ barrier counter reset) ----------------
__global__ void embed_kernel(const int* __restrict__ idx,
                             const float* __restrict__ emb,
                             float* __restrict__ out) {
    if (blockIdx.x == 0 && threadIdx.x < 8) g_bar[threadIdx.x] = 0u;   // reset per launch/replay
    int i = blockIdx.x * blockDim.x + threadIdx.x;     // float4 index
    const int total = T_SEQ * B_SZ * (E_SZ / 4);
    if (i >= total) return;
    int row = i >> 7;          // / (E/4=128)
    int col = i & 127;
    int tok = idx[row];
    reinterpret_cast<float4*>(out)[i] =
        reinterpret_cast<const float4*>(emb)[(size_t)tok * 128 + col];
}

// ---------------- fp32 GEMM: C[M,N] = A[M,K] * B[N,K]^T + bias[N] ----------------
// M=32768, N=1536, K=512. 128x128 tile, BK=16, 256 threads, 8x8 microtile.
// f32x2 math (A row-pairs native, B dup'd). Register double-buffered global loads.
#define BM 128
#define BN 128
#define BK 16

__global__ __launch_bounds__(256) void gemm_nt_bias(
    const float* __restrict__ A, const float* __restrict__ Bm,
    const float* __restrict__ bias, float* __restrict__ C,
    int M, int N, int K) {
    __shared__ float As[BK][BM];
    __shared__ float Bs[BK][BN];

    const int tid = threadIdx.x;
    const int bm = blockIdx.y * BM;
    const int bn = blockIdx.x * BN;
    const int tx = tid & 15;        // 0..15
    const int ty = tid >> 4;        // 0..15

    // staging indices for the two load slots
    const int f0 = tid;             // 0..255
    const int f1 = tid + 256;       // 256..511
    const int r0 = f0 >> 2, kq0 = (f0 & 3) << 2;
    const int r1 = f1 >> 2, kq1 = (f1 & 3) << 2;

    unsigned long long acc2[4][8];   // [row-pair ip][col j]: rows (ty*8+2ip, +1)
#pragma unroll
    for (int i = 0; i < 4; i++)
#pragma unroll
        for (int j = 0; j < 8; j++) acc2[i][j] = 0ULL;

    // prefetch first tile into registers
    float4 pa0 = *reinterpret_cast<const float4*>(&A[(size_t)(bm + r0) * K + kq0]);
    float4 pa1 = *reinterpret_cast<const float4*>(&A[(size_t)(bm + r1) * K + kq1]);
    float4 pb0 = *reinterpret_cast<const float4*>(&Bm[(size_t)(bn + r0) * K + kq0]);
    float4 pb1 = *reinterpret_cast<const float4*>(&Bm[(size_t)(bn + r1) * K + kq1]);

    for (int k0 = 0; k0 < K; k0 += BK) {
        // store staged tile
        As[kq0 + 0][r0] = pa0.x; As[kq0 + 1][r0] = pa0.y;
        As[kq0 + 2][r0] = pa0.z; As[kq0 + 3][r0] = pa0.w;
        As[kq1 + 0][r1] = pa1.x; As[kq1 + 1][r1] = pa1.y;
        As[kq1 + 2][r1] = pa1.z; As[kq1 + 3][r1] = pa1.w;
        Bs[kq0 + 0][r0] = pb0.x; Bs[kq0 + 1][r0] = pb0.y;
        Bs[kq0 + 2][r0] = pb0.z; Bs[kq0 + 3][r0] = pb0.w;
        Bs[kq1 + 0][r1] = pb1.x; Bs[kq1 + 1][r1] = pb1.y;
        Bs[kq1 + 2][r1] = pb1.z; Bs[kq1 + 3][r1] = pb1.w;
        __syncthreads();

        // prefetch next tile (overlaps with FMA loop below)
        if (k0 + BK < K) {
            int kn = k0 + BK;
            pa0 = *reinterpret_cast<const float4*>(&A[(size_t)(bm + r0) * K + kn + kq0]);
            pa1 = *reinterpret_cast<const float4*>(&A[(size_t)(bm + r1) * K + kn + kq1]);
            pb0 = *reinterpret_cast<const float4*>(&Bm[(size_t)(bn + r0) * K + kn + kq0]);
            pb1 = *reinterpret_cast<const float4*>(&Bm[(size_t)(bn + r1) * K + kn + kq1]);
        }

#pragma unroll
        for (int k = 0; k < BK; k++) {
            ulonglong2 aq0 = *reinterpret_cast<const ulonglong2*>(&As[k][ty * 8]);
            ulonglong2 aq1 = *reinterpret_cast<const ulonglong2*>(&As[k][ty * 8 + 4]);
            float4 b0 = *reinterpret_cast<const float4*>(&Bs[k][tx * 8]);
            float4 b1 = *reinterpret_cast<const float4*>(&Bs[k][tx * 8 + 4]);
            unsigned long long ap[4] = {aq0.x, aq0.y, aq1.x, aq1.y};
            unsigned long long bd[8] = {dup2(b0.x), dup2(b0.y), dup2(b0.z), dup2(b0.w),
                                        dup2(b1.x), dup2(b1.y), dup2(b1.z), dup2(b1.w)};
#pragma unroll
            for (int ip = 0; ip < 4; ip++)
#pragma unroll
                for (int j = 0; j < 8; j++) fma2(acc2[ip][j], ap[ip], bd[j]);
        }
        __syncthreads();
    }

    float bv[8];
    {
        float4 bias0 = *reinterpret_cast<const float4*>(&bias[bn + tx * 8]);
        float4 bias1 = *reinterpret_cast<const float4*>(&bias[bn + tx * 8 + 4]);
        bv[0] = bias0.x; bv[1] = bias0.y; bv[2] = bias0.z; bv[3] = bias0.w;
        bv[4] = bias1.x; bv[5] = bias1.y; bv[6] = bias1.z; bv[7] = bias1.w;
    }
#pragma unroll
    for (int ip = 0; ip < 4; ip++) {
        float lo[8], hi[8];
#pragma unroll
        for (int j = 0; j < 8; j++) {
            lo[j] = __uint_as_float((unsigned)acc2[ip][j]) + bv[j];
            hi[j] = __uint_as_float((unsigned)(acc2[ip][j] >> 32)) + bv[j];
        }
        int row0 = bm + ty * 8 + 2 * ip;
        float* cp0 = &C[(size_t)row0 * N + bn + tx * 8];
        float* cp1 = cp0 + N;
        *reinterpret_cast<float4*>(cp0)     = make_float4(lo[0], lo[1], lo[2], lo[3]);
        *reinterpret_cast<float4*>(cp0 + 4) = make_float4(lo[4], lo[5], lo[6], lo[7]);
        *reinterpret_cast<float4*>(cp1)     = make_float4(hi[0], hi[1], hi[2], hi[3]);
        *reinterpret_cast<float4*>(cp1 + 4) = make_float4(hi[4], hi[5], hi[6], hi[7]);
    }
}

// ---------------- persistent GRU recurrence ----------------
// Grid = 128 CTAs = 8 batch-groups x 16 e-groups, 256 threads = 8 warps.
// Batch groups are fully independent -> each bg has its own monotonic barrier
// counter; only the 16 eg-CTAs of a bg synchronize with each other.
// Dot phase: warp w handles k-slice [w*64, w*64+64) for ALL 8 batch rows.
// Reduce phase: thread (b = tid>>5, jg = tid&31) sums the 8 warp-partials/gate.
#define RGRID 128
#define EGROUPS 16
#define BTILE 8
#define ESLICE 32
#define WROWS 96
#define WSTR 516
#define PART_FLOATS (8 * 3 * BTILE * ESLICE)         // 6144
#define RSMEM_FLOATS (WROWS * WSTR + PART_FLOATS)
#define RSMEM_BYTES (RSMEM_FLOATS * 4)

__device__ __forceinline__ void bg_arrive(unsigned* ctr) {
    asm volatile("red.release.gpu.global.add.u32 [%0], %1;" :: "l"(ctr), "r"(1u) : "memory");
}
__device__ __forceinline__ void bg_wait(unsigned* ctr, unsigned target) {
    unsigned cur;
    do {
        asm volatile("ld.acquire.gpu.u32 %0, [%1];" : "=r"(cur) : "l"(ctr) : "memory");
    } while ((int)(cur - target) < 0);
}

__global__ __launch_bounds__(256, 1) void gru_recur_kernel(
    const float* __restrict__ xproj,   // [T,64,1536]
    const float* __restrict__ Whh,     // [1536,512] (this layer)
    const float* __restrict__ bhh,     // [1536]
    const int* __restrict__ lens,      // [64]
    float* __restrict__ hbuf,          // [64,512]
    float* __restrict__ ybuf,          // [T,64,512]
    float* __restrict__ finals,        // [64,512]
    int epoch)                         // layer index (barrier target base)
{
    extern __shared__ float smem[];
    float* sh_w = smem;                       // WROWS * WSTR
    float* sh_h = smem + WROWS * WSTR;        // 8*512 floats (dot phase)
    float* sh_part = sh_h;                    // 8*768 floats (reduce phase, overlapped)

    const int tid = threadIdx.x;
    const int cta = blockIdx.x;
    const int bg = cta / EGROUPS;
    const int eg = cta % EGROUPS;
    const int ebase = eg * ESLICE;
    const int w = tid >> 5;            // dot phase: k-slice warp 0..7
    const int jg = tid & 31;           // lane = local e 0..31
    const int bR = w;                  // reduce phase: local batch row 0..7
    const int bglob = bg * BTILE + bR;
    const int e = ebase + jg;
    const int kbase = w * 64;
    unsigned* ctr = &g_bar[bg];
    const unsigned tbase = (unsigned)epoch * (16u * (T_SEQ + 1)) + 16u;

    // Load this CTA's 96 weight rows (float4), interleaved: row j = elocal*3 + gate
    for (int idx = tid; idx < WROWS * (E_SZ / 4); idx += 256) {
        int j = idx >> 7;                 // / 128
        int kq = (idx & 127) << 2;
        int el = j / 3, gate = j - el * 3;
        *reinterpret_cast<float4*>(&sh_w[j * WSTR + kq]) =
            *reinterpret_cast<const float4*>(&Whh[(size_t)(gate * E_SZ + ebase + el) * E_SZ + kq]);
    }

    const float bh0 = bhh[0 * E_SZ + e];
    const float bh1 = bhh[1 * E_SZ + e];
    const float bh2 = bhh[2 * E_SZ + e];
    const int mylen = lens[bglob];

    // zero our slice of h, arrive, prefetch xp(t=0), wait for the 16 eg-CTAs
    hbuf[bglob * E_SZ + e] = 0.f;
    __syncthreads();                 // everyone's store issued before tid0 signals
    if (tid == 0) bg_arrive(ctr);

    float xr, xz, xn;
    {
        const float* xp = xproj + ((size_t)0 * B_SZ + bglob) * G3E;
        xr = xp[e]; xz = xp[E_SZ + e]; xn = xp[2 * E_SZ + e];
    }
    if (tid == 0) bg_wait(ctr, tbase);
    __syncthreads();

    const float* wp0 = sh_w + (jg * 3 + 0) * WSTR;
    const float* wp1 = wp0 + WSTR;
    const float* wp2 = wp1 + WSTR;

    float hnew = 0.f;

    for (int t = 0; t < T_SEQ; t++) {
        // Stage h tile (8 rows x 512) into smem, coalesced float4
        {
            const float4* hsrc = reinterpret_cast<const float4*>(hbuf + bg * BTILE * E_SZ);
            float4* hdst = reinterpret_cast<float4*>(sh_h);
#pragma unroll
            for (int i = 0; i < 4; i++) hdst[tid + i * 256] = hsrc[tid + i * 256];
        }
        __syncthreads();

        float hprev = sh_h[bR * E_SZ + e];   // read before partials overwrite region

        // ---- dot phase: 64 k x 3 gates x 8 batch, f32x2 packed ----
        unsigned long long a0[8], a1[8], a2[8];
#pragma unroll
        for (int b = 0; b < 8; b++) { a0[b] = 0ULL; a1[b] = 0ULL; a2[b] = 0ULL; }

#pragma unroll 4
        for (int kk = 0; kk < 16; kk++) {
            int k4 = kbase + kk * 4;
            ulonglong2 w0 = *reinterpret_cast<const ulonglong2*>(wp0 + k4);
            ulonglong2 w1 = *reinterpret_cast<const ulonglong2*>(wp1 + k4);
            ulonglong2 w2 = *reinterpret_cast<const ulonglong2*>(wp2 + k4);
#pragma unroll
            for (int b = 0; b < 8; b++) {
                ulonglong2 h2 = *reinterpret_cast<const ulonglong2*>(sh_h + b * E_SZ + k4);
                fma2(a0[b], h2.x, w0.x); fma2(a0[b], h2.y, w0.y);
                fma2(a1[b], h2.x, w1.x); fma2(a1[b], h2.y, w1.y);
                fma2(a2[b], h2.x, w2.x); fma2(a2[b], h2.y, w2.y);
            }
        }

        __syncthreads();   // all warps done reading sh_h

        // ---- store partials: part[w][gate][b][lane] ----
        {
            float* pw = sh_part + w * (3 * BTILE * ESLICE);
#pragma unroll
            for (int b = 0; b < 8; b++) {
                pw[(0 * BTILE + b) * ESLICE + jg] = f32x2_sum(a0[b]);
                pw[(1 * BTILE + b) * ESLICE + jg] = f32x2_sum(a1[b]);
                pw[(2 * BTILE + b) * ESLICE + jg] = f32x2_sum(a2[b]);
            }
        }
        __syncthreads();

        // ---- reduce phase: thread (bR, jg) sums 8 warp partials per gate ----
        float s0 = 0.f, s1 = 0.f, s2 = 0.f;
#pragma unroll
        for (int ww = 0; ww < 8; ww++) {
            const float* pw = sh_part + ww * (3 * BTILE * ESLICE);
            s0 += pw[(0 * BTILE + bR) * ESLICE + jg];
            s1 += pw[(1 * BTILE + bR) * ESLICE + jg];
            s2 += pw[(2 * BTILE + bR) * ESLICE + jg];
        }

        float hr = s0 + bh0, hz = s1 + bh1, hn = s2 + bh2;
        float r = 1.f / (1.f + expf(-(xr + hr)));
        float z = 1.f / (1.f + expf(-(xz + hz)));
        float n = tanhf(xn + r * hn);
        bool m = (t < mylen);
        hnew = m ? ((1.f - z) * n + z * hprev) : hprev;

        hbuf[bglob * E_SZ + e] = hnew;

        __syncthreads();                // all h stores issued before the signal
        if (tid == 0) bg_arrive(ctr);

        // overlap with barrier wait: y store + next xp prefetch
        ybuf[((size_t)t * B_SZ + bglob) * E_SZ + e] = m ? hnew : 0.f;
        if (t + 1 < T_SEQ) {
            const float* xp = xproj + ((size_t)(t + 1) * B_SZ + bglob) * G3E;
            xr = xp[e]; xz = xp[E_SZ + e]; xn = xp[2 * E_SZ + e];
        }

        if (tid == 0) bg_wait(ctr, tbase + 16u * (t + 1));
        __syncthreads();
    }

    finals[bglob * E_SZ + e] = hnew;
}

// ---------------- launch ----------------
extern "C" void kernel_launch(void* const* d_in, const int* in_sizes, int n_in,
                              void* d_out, int out_size) {
    const int*   input_batch = (const int*)d_in[0];
    const int*   lens        = (const int*)d_in[1];
    const float* emb         = (const float*)d_in[2];
    const float* W_ih        = (const float*)d_in[3];
    const float* W_hh        = (const float*)d_in[4];
    const float* b_ih        = (const float*)d_in[5];
    const float* b_hh        = (const float*)d_in[6];
    float* out = (float*)d_out;

    void* p;
    cudaGetSymbolAddress(&p, g_x);     float* gx  = (float*)p;
    cudaGetSymbolAddress(&p, g_xproj); float* gxp = (float*)p;
    cudaGetSymbolAddress(&p, g_h);     float* gh  = (float*)p;

    cudaFuncSetAttribute(gru_recur_kernel,
                         cudaFuncAttributeMaxDynamicSharedMemorySize, RSMEM_BYTES);

    const int M = T_SEQ * B_SZ;        // 32768
    const size_t out_x_elems = (size_t)T_SEQ * B_SZ * E_SZ;   // 16777216
    float* finals0 = out + out_x_elems;
    float* finals1 = out + out_x_elems + B_SZ * E_SZ;

    // 1. embeddings (+ barrier reset)
    {
        int total = T_SEQ * B_SZ * (E_SZ / 4);
        embed_kernel<<<(total + 255) / 256, 256>>>(input_batch, emb, gx);
    }
    // 2. layer 0 input projection
    gemm_nt_bias<<<dim3(G3E / BN, M / BM), 256>>>(gx, W_ih, b_ih, gxp, M, G3E, E_SZ);
    // 3. layer 0 recurrence: y -> gx (reuse), finals -> d_out hidden[0]
    gru_recur_kernel<<<RGRID, 256, RSMEM_BYTES>>>(gxp, W_hh, b_hh, lens, gh, gx, finals0, 0);
    // 4. layer 1 input projection
    gemm_nt_bias<<<dim3(G3E / BN, M / BM), 256>>>(gx, W_ih + (size_t)G3E * E_SZ,
                                                  b_ih + G3E, gxp, M, G3E, E_SZ);
    // 5. layer 1 recurrence: y -> d_out[0:T*B*E], finals -> d_out hidden[1]
    gru_recur_kernel<<<RGRID, 256, RSMEM_BYTES>>>(gxp, W_hh + (size_t)G3E * E_SZ,
                                                  b_hh + G3E, lens, gh, out, finals1, 1);
}